// round 15
// baseline (speedup 1.0000x reference)
#include <cuda_runtime.h>
#include <cuda_fp16.h>
#include <cstdint>

// ---------------- problem dims (fixed) ----------------
#define Bc   2
#define LQ   1024
#define LKV  4096
#define Dm   512
#define NH   8
#define DHd  64
#define Ff   2048
#define MQ   (Bc*LQ)    // 2048
#define MKV  (Bc*LKV)   // 8192
#define SPLIT 4
#define TKV  (LKV / 64 / SPLIT)   // 16

// ---------------- scratch (device globals) ----------------
__device__ __half hb_ln [MQ*Dm];
__device__ __half hb_kvf[MKV*Dm];
__device__ __half hb_kvo[MKV*Dm];
__device__ __half hb_fsr[MKV*Dm];
__device__ __half hb_osr[MKV*Dm];
__device__ __half hb_Q  [MQ*Dm];
__device__ __half hb_K  [MKV*Dm];
__device__ __half hb_V  [MKV*Dm];
__device__ __half hb_Ko [MKV*Dm];
__device__ __half hb_Vo [MKV*Dm];
__device__ __half hb_at [MQ*Dm];
__device__ __half hb_h1 [MQ*Ff];
__device__ __half hb_WT [8*262144 + 2*1048576];
__device__ float  g_x   [MQ*Dm];
__device__ float  g_part[SPLIT*MQ*Dm];
__device__ float  g_ml  [SPLIT*MQ*NH*2];

// ---------------- helpers ----------------
__device__ __forceinline__ uint32_t packh2(float a, float b) {
    __half2 h = __floats2half2_rn(a, b);
    return *(uint32_t*)&h;
}
__device__ __forceinline__ float ex2(float x) {
    float y; asm("ex2.approx.f32 %0, %1;" : "=f"(y) : "f"(x)); return y;
}
__device__ __forceinline__ void cpa16(uint32_t dst, const void* src) {
    asm volatile("cp.async.cg.shared.global [%0], [%1], 16;" :: "r"(dst), "l"(src));
}
__device__ __forceinline__ void cpa_commit() {
    asm volatile("cp.async.commit_group;" ::: "memory");
}
template <int N> __device__ __forceinline__ void cpa_wait() {
    asm volatile("cp.async.wait_group %0;" :: "n"(N) : "memory");
}
__device__ __forceinline__ void mma_f16(float c[4], const uint32_t a[4],
                                        uint32_t b0, uint32_t b1) {
    asm("mma.sync.aligned.m16n8k16.row.col.f32.f16.f16.f32 "
        "{%0,%1,%2,%3},{%4,%5,%6,%7},{%8,%9},{%0,%1,%2,%3};"
        : "+f"(c[0]), "+f"(c[1]), "+f"(c[2]), "+f"(c[3])
        : "r"(a[0]), "r"(a[1]), "r"(a[2]), "r"(a[3]), "r"(b0), "r"(b1));
}
__device__ __forceinline__ void ldsm_x4(uint32_t& r0, uint32_t& r1, uint32_t& r2,
                                        uint32_t& r3, uint32_t addr) {
    asm volatile("ldmatrix.sync.aligned.m8n8.x4.shared.b16 {%0,%1,%2,%3},[%4];"
        : "=r"(r0), "=r"(r1), "=r"(r2), "=r"(r3) : "r"(addr));
}
__device__ __forceinline__ void ldsm_x4_t(uint32_t& r0, uint32_t& r1, uint32_t& r2,
                                          uint32_t& r3, uint32_t addr) {
    asm volatile("ldmatrix.sync.aligned.m8n8.x4.trans.shared.b16 {%0,%1,%2,%3},[%4];"
        : "=r"(r0), "=r"(r1), "=r"(r2), "=r"(r3) : "r"(addr));
}

// ---------------- per-segment prep ----------------
// seg: 0 copy fs->out, 1 copy os->out, 2 fs->fsr(h), 3 os->osr(h),
//      4 fs+fpe->kvf(h), 5 os+ope->kvo(h)
__global__ void prep_seg_k(int seg,
                           const float* __restrict__ fs, const float* __restrict__ fpe,
                           const float* __restrict__ os_, const float* __restrict__ ope,
                           float* __restrict__ out, __half* __restrict__ fsr,
                           __half* __restrict__ osr, __half* __restrict__ kvf,
                           __half* __restrict__ kvo) {
    const int i = blockIdx.x * 256 + threadIdx.x;
    switch (seg) {
    case 0: ((float4*)(out + (size_t)MQ * Dm))[i] = ((const float4*)fs)[i]; break;
    case 1: ((float4*)(out + (size_t)MQ * Dm + (size_t)MKV * Dm))[i] = ((const float4*)os_)[i]; break;
    case 2: { float4 v = ((const float4*)fs)[i];
              ((uint2*)fsr)[i] = make_uint2(packh2(v.x, v.y), packh2(v.z, v.w)); break; }
    case 3: { float4 v = ((const float4*)os_)[i];
              ((uint2*)osr)[i] = make_uint2(packh2(v.x, v.y), packh2(v.z, v.w)); break; }
    case 4: { float4 a = ((const float4*)fs)[i], b = ((const float4*)fpe)[i];
              ((uint2*)kvf)[i] = make_uint2(packh2(a.x + b.x, a.y + b.y),
                                            packh2(a.z + b.z, a.w + b.w)); break; }
    default:{ float4 a = ((const float4*)os_)[i], b = ((const float4*)ope)[i];
              ((uint2*)kvo)[i] = make_uint2(packh2(a.x + b.x, a.y + b.y),
                                            packh2(a.z + b.z, a.w + b.w)); break; }
    }
}

// ---------------- fused weight transpose ----------------
struct TWSeg { const float* src; __half* dst; int K; int N; int tiles; };
struct TWTab { TWSeg s[10]; };
__global__ void tWall_k(TWTab tab) {
    __shared__ float t[32][33];
    int tI = blockIdx.x, j = 0;
#pragma unroll
    for (int q = 0; q < 9; q++) if (tI >= tab.s[j].tiles) { tI -= tab.s[j].tiles; j++; }
    const float* W = tab.s[j].src;
    __half* WT = tab.s[j].dst;
    const int K = tab.s[j].K, N = tab.s[j].N;
    const int ntx = N >> 5;
    const int n0 = (tI % ntx) * 32, k0 = (tI / ntx) * 32;
    const int tx = threadIdx.x, ty = threadIdx.y;
#pragma unroll
    for (int r = 0; r < 32; r += 8)
        t[ty + r][tx] = W[(size_t)(k0 + ty + r) * N + n0 + tx];
    __syncthreads();
#pragma unroll
    for (int r = 0; r < 32; r += 8)
        WT[(size_t)(n0 + ty + r) * K + k0 + tx] = __float2half_rn(t[tx][ty + r]);
}

// ---------------- layernorm (+ optional pe), half output ----------------
__global__ void ln_pe_k(const float* __restrict__ x, const float* __restrict__ g,
                        const float* __restrict__ b, const float* __restrict__ pe,
                        __half* __restrict__ out) {
    __shared__ float red[8];
    const int row = blockIdx.x, tid = threadIdx.x;
    const float* xr = x + (size_t)row * Dm;
    float4 xv = *(const float4*)&xr[tid * 4];
    float sum = xv.x + xv.y + xv.z + xv.w;
    float sq  = xv.x*xv.x + xv.y*xv.y + xv.z*xv.z + xv.w*xv.w;
#pragma unroll
    for (int off = 16; off > 0; off >>= 1) {
        sum += __shfl_xor_sync(0xffffffffu, sum, off);
        sq  += __shfl_xor_sync(0xffffffffu, sq,  off);
    }
    if ((tid & 31) == 0) { red[tid >> 5] = sum; red[4 + (tid >> 5)] = sq; }
    __syncthreads();
    sum = red[0] + red[1] + red[2] + red[3];
    sq  = red[4] + red[5] + red[6] + red[7];
    float mu   = sum * (1.0f / Dm);
    float var  = sq * (1.0f / Dm) - mu * mu;
    float rstd = rsqrtf(var + 1e-6f);
    float4 gv = *(const float4*)&g[tid * 4];
    float4 bv = *(const float4*)&b[tid * 4];
    float4 r;
    r.x = (xv.x - mu) * rstd * gv.x + bv.x;
    r.y = (xv.y - mu) * rstd * gv.y + bv.y;
    r.z = (xv.z - mu) * rstd * gv.z + bv.z;
    r.w = (xv.w - mu) * rstd * gv.w + bv.w;
    if (pe) {
        const float4 pv = *(const float4*)&pe[(size_t)row * Dm + tid * 4];
        r.x += pv.x; r.y += pv.y; r.z += pv.z; r.w += pv.w;
    }
    *(uint2*)&out[(size_t)row * Dm + tid * 4] = make_uint2(packh2(r.x, r.y), packh2(r.z, r.w));
}

// ---------------- fp16 GEMM, cp.async 3-stage, ldmatrix, templated BN ----------------
#define APITCH 40

template <int BN, bool RELU, bool RES, bool HOUT>
__global__ void __launch_bounds__(128) tgemm_k(
    const __half* __restrict__ A, const __half* __restrict__ WT,
    const float* __restrict__ bias, const float* __restrict__ res,
    void* __restrict__ C, int M, int N, int K, float scale)
{
    constexpr int NI   = BN / 16;
    constexpr int BP   = BN / 32;
    constexpr int GST  = (64 + BN) * APITCH * 2;
    extern __shared__ __half smh[];
    const int tid = threadIdx.x, lane = tid & 31, w = tid >> 5;
    const int wm = w >> 1, wn = w & 1;
    const int g = lane >> 2, qd = lane & 3;
    const int m0 = blockIdx.y * 64, n0 = blockIdx.x * BN;
    const uint32_t sbase = (uint32_t)__cvta_generic_to_shared(smh);

    const int fra = tid >> 1, fca = (tid & 1) * 16;
    const __half* aSrc = A + (size_t)(m0 + fra) * K + fca;
    const uint32_t aDst = sbase + (fra * APITCH + fca) * 2;
    const int frb = (BP == 2) ? (tid >> 1) : tid;
    const int fcb = (BP == 2) ? ((tid & 1) * 16) : 0;
    const __half* bSrc = WT + (size_t)(n0 + frb) * K + fcb;
    const uint32_t bDst = sbase + ((64 + frb) * APITCH + fcb) * 2;

    const int L = lane;
    const uint32_t aOff = ((wm * 32 + ((L >> 3) & 1) * 8 + (L & 7)) * APITCH
                           + (L >> 4) * 8) * 2;
    const uint32_t bOff = ((64 + wn * (BN / 2) + (L >> 4) * 8 + (L & 7)) * APITCH
                           + ((L >> 3) & 1) * 8) * 2;

    const int KT = K >> 5;
#pragma unroll
    for (int pre = 0; pre < 2; pre++) {
        const __half* sa = aSrc + pre * 32;
        const __half* sb = bSrc + pre * 32;
        uint32_t da = aDst + pre * GST, db = bDst + pre * GST;
        cpa16(da, sa); cpa16(da + 16, sa + 8);
#pragma unroll
        for (int i = 0; i < ((BP == 2) ? 2 : 4); i++)
            cpa16(db + i * 16, sb + i * 8);
        cpa_commit();
    }

    float acc[2][NI][4];
#pragma unroll
    for (int mi = 0; mi < 2; mi++)
#pragma unroll
        for (int ni = 0; ni < NI; ni++)
#pragma unroll
            for (int e = 0; e < 4; e++) acc[mi][ni][e] = 0.f;

    for (int kt = 0; kt < KT; kt++) {
        cpa_wait<1>();
        __syncthreads();
        if (kt + 2 < KT) {
            int s2 = (kt + 2) % 3;
            const __half* sa = aSrc + (kt + 2) * 32;
            const __half* sb = bSrc + (kt + 2) * 32;
            uint32_t da = aDst + s2 * GST, db = bDst + s2 * GST;
            cpa16(da, sa); cpa16(da + 16, sa + 8);
#pragma unroll
            for (int i = 0; i < ((BP == 2) ? 2 : 4); i++)
                cpa16(db + i * 16, sb + i * 8);
        }
        cpa_commit();
        const uint32_t st = sbase + (kt % 3) * GST;
#pragma unroll
        for (int ks = 0; ks < 2; ks++) {
            uint32_t af[2][4], bf[NI][2];
#pragma unroll
            for (int mi = 0; mi < 2; mi++)
                ldsm_x4(af[mi][0], af[mi][1], af[mi][2], af[mi][3],
                        st + aOff + (mi * 16 * APITCH + ks * 16) * 2);
#pragma unroll
            for (int p = 0; p < BP; p++) {
                uint32_t r0, r1, r2, r3;
                ldsm_x4(r0, r1, r2, r3, st + bOff + (p * 16 * APITCH + ks * 16) * 2);
                bf[2*p][0] = r0; bf[2*p][1] = r1;
                bf[2*p+1][0] = r2; bf[2*p+1][1] = r3;
            }
#pragma unroll
            for (int mi = 0; mi < 2; mi++)
#pragma unroll
                for (int ni = 0; ni < NI; ni++)
                    mma_f16(acc[mi][ni], af[mi], bf[ni][0], bf[ni][1]);
        }
    }

#pragma unroll
    for (int mi = 0; mi < 2; mi++) {
        int mrow = m0 + wm * 32 + mi * 16 + g;
#pragma unroll
        for (int ni = 0; ni < NI; ni++) {
            int ncol = n0 + wn * (BN / 2) + ni * 8 + 2 * qd;
            float2 bv = *(const float2*)&bias[ncol];
#pragma unroll
            for (int hh = 0; hh < 2; hh++) {
                size_t m = (size_t)(mrow + hh * 8);
                float vx = acc[mi][ni][hh * 2 + 0] + bv.x;
                float vy = acc[mi][ni][hh * 2 + 1] + bv.y;
                if (RELU) { vx = fmaxf(vx, 0.f); vy = fmaxf(vy, 0.f); }
                vx *= scale; vy *= scale;
                if (HOUT) {
                    *(__half2*)((__half*)C + m * N + ncol) = __floats2half2_rn(vx, vy);
                } else {
                    if (RES) {
                        float2 rv = *(const float2*)&res[m * N + ncol];
                        vx += rv.x; vy += rv.y;
                    }
                    *(float2*)((float*)C + m * N + ncol) = make_float2(vx, vy);
                }
            }
        }
    }
}

// ---------------- fp16 flash attention, kv-split, double-buffered ----------------
#define FPITCH 72
#define QB  (64 * FPITCH * 2)
#define ATTN_SMEM (5 * QB)

__global__ void __launch_bounds__(64) fattn_k(
    const __half* __restrict__ Qm, const __half* __restrict__ Km,
    const __half* __restrict__ Vm, float* __restrict__ part, float* __restrict__ ml)
{
    extern __shared__ __half smf[];
    const uint32_t sbase = (uint32_t)__cvta_generic_to_shared(smf);
    const uint32_t sQ = sbase;

    const int tid = threadIdx.x;
    const int lane = tid & 31, w = tid >> 5;
    const int g = lane >> 2, qd = lane & 3;
    const int bb = blockIdx.z / SPLIT, sp = blockIdx.z % SPLIT;
    const int hh = blockIdx.y, qt = blockIdx.x;
    const size_t qrow0 = (size_t)bb * LQ + qt * 64;
    const int hoff = hh * DHd;
    const int mb = w * 32;
    const int L = lane;

    const int frr = tid >> 3, fcc = (tid & 7);
#pragma unroll
    for (int it = 0; it < 8; it++) {
        int r = frr + it * 8;
        cpa16(sQ + (r * FPITCH + fcc * 8) * 2, &Qm[(qrow0 + r) * Dm + hoff + fcc * 8]);
    }
    size_t kvb = (size_t)bb * LKV + (size_t)sp * TKV * 64;
#pragma unroll
    for (int it = 0; it < 8; it++) {
        int r = frr + it * 8;
        size_t gi = (kvb + r) * Dm + hoff + fcc * 8;
        cpa16(sQ + QB + (r * FPITCH + fcc * 8) * 2,     &Km[gi]);
        cpa16(sQ + 2 * QB + (r * FPITCH + fcc * 8) * 2, &Vm[gi]);
    }
    cpa_commit();
#pragma unroll
    for (int it = 0; it < 8; it++) {
        int r = frr + it * 8;
        size_t gi = (kvb + 64 + r) * Dm + hoff + fcc * 8;
        cpa16(sQ + 3 * QB + (r * FPITCH + fcc * 8) * 2, &Km[gi]);
        cpa16(sQ + 4 * QB + (r * FPITCH + fcc * 8) * 2, &Vm[gi]);
    }
    cpa_commit();

    const uint32_t qOff = ((mb + ((L >> 3) & 1) * 8 + (L & 7)) * FPITCH + (L >> 4) * 8) * 2;
    const uint32_t kOff = (((L >> 4) * 8 + (L & 7)) * FPITCH + ((L >> 3) & 1) * 8) * 2;
    const uint32_t vOff = ((L & 15) * FPITCH + (L >> 4) * 8) * 2;

    uint32_t aq[2][4][4];
    float o[2][8][4] = {};
    float mr[2][2] = {{-1e30f, -1e30f}, {-1e30f, -1e30f}};
    float lr[2][2] = {{0.f, 0.f}, {0.f, 0.f}};

    for (int t = 0; t < TKV; t++) {
        cpa_wait<1>();
        __syncthreads();
        if (t == 0) {
#pragma unroll
            for (int mi = 0; mi < 2; mi++)
#pragma unroll
                for (int ks = 0; ks < 4; ks++)
                    ldsm_x4(aq[mi][ks][0], aq[mi][ks][1], aq[mi][ks][2], aq[mi][ks][3],
                            sQ + qOff + (mi * 16 * FPITCH + ks * 16) * 2);
        }
        const uint32_t sK = sQ + QB + (t & 1) * 2 * QB;
        const uint32_t sV = sK + QB;

        float s[2][8][4] = {};
#pragma unroll
        for (int ks = 0; ks < 4; ks++) {
            uint32_t kb[8][2];
#pragma unroll
            for (int p = 0; p < 4; p++) {
                uint32_t r0, r1, r2, r3;
                ldsm_x4(r0, r1, r2, r3, sK + kOff + (p * 16 * FPITCH + ks * 16) * 2);
                kb[2*p][0] = r0; kb[2*p][1] = r1;
                kb[2*p+1][0] = r2; kb[2*p+1][1] = r3;
            }
#pragma unroll
            for (int mi = 0; mi < 2; mi++)
#pragma unroll
                for (int ni = 0; ni < 8; ni++)
                    mma_f16(s[mi][ni], aq[mi][ks], kb[ni][0], kb[ni][1]);
        }

        float es[2][2];
#pragma unroll
        for (int mi = 0; mi < 2; mi++) {
            float mx0 = -1e30f, mx1 = -1e30f;
#pragma unroll
            for (int ni = 0; ni < 8; ni++) {
                mx0 = fmaxf(mx0, fmaxf(s[mi][ni][0], s[mi][ni][1]));
                mx1 = fmaxf(mx1, fmaxf(s[mi][ni][2], s[mi][ni][3]));
            }
            mx0 = fmaxf(mx0, __shfl_xor_sync(~0u, mx0, 1));
            mx0 = fmaxf(mx0, __shfl_xor_sync(~0u, mx0, 2));
            mx1 = fmaxf(mx1, __shfl_xor_sync(~0u, mx1, 1));
            mx1 = fmaxf(mx1, __shfl_xor_sync(~0u, mx1, 2));
            float mn0 = fmaxf(mr[mi][0], mx0), mn1 = fmaxf(mr[mi][1], mx1);
            float sum0 = 0.f, sum1 = 0.f;
#pragma unroll
            for (int ni = 0; ni < 8; ni++) {
                s[mi][ni][0] = ex2(s[mi][ni][0] - mn0);
                s[mi][ni][1] = ex2(s[mi][ni][1] - mn0);
                s[mi][ni][2] = ex2(s[mi][ni][2] - mn1);
                s[mi][ni][3] = ex2(s[mi][ni][3] - mn1);
                sum0 += s[mi][ni][0] + s[mi][ni][1];
                sum1 += s[mi][ni][2] + s[mi][ni][3];
            }
            sum0 += __shfl_xor_sync(~0u, sum0, 1); sum0 += __shfl_xor_sync(~0u, sum0, 2);
            sum1 += __shfl_xor_sync(~0u, sum1, 1); sum1 += __shfl_xor_sync(~0u, sum1, 2);
            es[mi][0] = ex2(mr[mi][0] - mn0); es[mi][1] = ex2(mr[mi][1] - mn1);
            mr[mi][0] = mn0; mr[mi][1] = mn1;
            lr[mi][0] = lr[mi][0] * es[mi][0] + sum0;
            lr[mi][1] = lr[mi][1] * es[mi][1] + sum1;
#pragma unroll
            for (int ni = 0; ni < 8; ni++) {
                o[mi][ni][0] *= es[mi][0]; o[mi][ni][1] *= es[mi][0];
                o[mi][ni][2] *= es[mi][1]; o[mi][ni][3] *= es[mi][1];
            }
        }

#pragma unroll
        for (int ks = 0; ks < 4; ks++) {
            uint32_t vb[8][2];
#pragma unroll
            for (int j = 0; j < 4; j++) {
                uint32_t r0, r1, r2, r3;
                ldsm_x4_t(r0, r1, r2, r3, sV + vOff + (ks * 16 * FPITCH + j * 16) * 2);
                vb[2*j][0] = r0; vb[2*j][1] = r1;
                vb[2*j+1][0] = r2; vb[2*j+1][1] = r3;
            }
            uint32_t ap[2][4];
#pragma unroll
            for (int mi = 0; mi < 2; mi++) {
                ap[mi][0] = packh2(s[mi][2*ks][0],   s[mi][2*ks][1]);
                ap[mi][1] = packh2(s[mi][2*ks][2],   s[mi][2*ks][3]);
                ap[mi][2] = packh2(s[mi][2*ks+1][0], s[mi][2*ks+1][1]);
                ap[mi][3] = packh2(s[mi][2*ks+1][2], s[mi][2*ks+1][3]);
            }
#pragma unroll
            for (int mi = 0; mi < 2; mi++)
#pragma unroll
                for (int ni = 0; ni < 8; ni++)
                    mma_f16(o[mi][ni], ap[mi], vb[ni][0], vb[ni][1]);
        }

        __syncthreads();
        if (t + 2 < TKV) {
            size_t kv0 = kvb + (size_t)(t + 2) * 64;
            uint32_t dK = sQ + QB + (t & 1) * 2 * QB;
#pragma unroll
            for (int it = 0; it < 8; it++) {
                int r = frr + it * 8;
                size_t gi = (kv0 + r) * Dm + hoff + fcc * 8;
                cpa16(dK + (r * FPITCH + fcc * 8) * 2,      &Km[gi]);
                cpa16(dK + QB + (r * FPITCH + fcc * 8) * 2, &Vm[gi]);
            }
        }
        cpa_commit();
    }

#pragma unroll
    for (int mi = 0; mi < 2; mi++) {
        int rloc = mb + mi * 16 + g;
#pragma unroll
        for (int ni = 0; ni < 8; ni++) {
            int ncol = hoff + ni * 8 + 2 * qd;
            *(float2*)&part[((size_t)sp * MQ + qrow0 + rloc) * Dm + ncol] =
                make_float2(o[mi][ni][0], o[mi][ni][1]);
            *(float2*)&part[((size_t)sp * MQ + qrow0 + rloc + 8) * Dm + ncol] =
                make_float2(o[mi][ni][2], o[mi][ni][3]);
        }
        if (qd == 0) {
            size_t b0 = (((size_t)sp * MQ + qrow0 + rloc) * NH + hh) * 2;
            ml[b0] = mr[mi][0]; ml[b0 + 1] = lr[mi][0];
            size_t b1 = (((size_t)sp * MQ + qrow0 + rloc + 8) * NH + hh) * 2;
            ml[b1] = mr[mi][1]; ml[b1 + 1] = lr[mi][1];
        }
    }
}

// ---------------- split combine (half output) ----------------
__global__ void comb_k(const float* __restrict__ part, const float* __restrict__ ml,
                       __half* __restrict__ out) {
    int row = blockIdx.x, tid = threadIdx.x;
    int c = tid * 4, h = c >> 6;
    float m[SPLIT], l[SPLIT];
#pragma unroll
    for (int sp = 0; sp < SPLIT; sp++) {
        const float* p = &ml[(((size_t)sp * MQ + row) * NH + h) * 2];
        m[sp] = p[0]; l[sp] = p[1];
    }
    float M = m[0];
#pragma unroll
    for (int sp = 1; sp < SPLIT; sp++) M = fmaxf(M, m[sp]);
    float s[SPLIT], Lh = 0.f;
#pragma unroll
    for (int sp = 0; sp < SPLIT; sp++) { s[sp] = ex2(m[sp] - M); Lh += l[sp] * s[sp]; }
    float inv = 1.f / Lh;
    float4 a = make_float4(0.f, 0.f, 0.f, 0.f);
#pragma unroll
    for (int sp = 0; sp < SPLIT; sp++) {
        float4 v = *(const float4*)&part[((size_t)sp * MQ + row) * Dm + c];
        a.x += v.x * s[sp]; a.y += v.y * s[sp];
        a.z += v.z * s[sp]; a.w += v.w * s[sp];
    }
    *(uint2*)&out[(size_t)row * Dm + c] =
        make_uint2(packh2(a.x * inv, a.y * inv), packh2(a.z * inv, a.w * inv));
}

// ---------------- host ----------------
#define GSMEM64  (3 * (64 + 64)  * APITCH * 2)
#define GSMEM128 (3 * (64 + 128) * APITCH * 2)

static cudaStream_t g_sA = nullptr, g_sB = nullptr;
static cudaEvent_t g_evRoot, g_evW, g_evKf, g_evVf, g_evKo, g_evVo, g_evA;

extern "C" void kernel_launch(void* const* d_in, const int* in_sizes, int n_in,
                              void* d_out, int out_size) {
    const float* hs  = (const float*)d_in[0];
    const float* hpe = (const float*)d_in[1];
    const float* fs  = (const float*)d_in[2];
    const float* fpe = (const float*)d_in[3];
    const float* os_ = (const float*)d_in[4];
    const float* ope = (const float*)d_in[5];
    const float* f_Wq = (const float*)d_in[6],  *f_Wk = (const float*)d_in[7];
    const float* f_Wv = (const float*)d_in[8],  *f_Wo = (const float*)d_in[9];
    const float* f_bq = (const float*)d_in[10], *f_bk = (const float*)d_in[11];
    const float* f_bv = (const float*)d_in[12], *f_bo = (const float*)d_in[13];
    const float* f_g  = (const float*)d_in[14], *f_b  = (const float*)d_in[15];
    const float* o_Wq = (const float*)d_in[16], *o_Wk = (const float*)d_in[17];
    const float* o_Wv = (const float*)d_in[18], *o_Wo = (const float*)d_in[19];
    const float* o_bq = (const float*)d_in[20], *o_bk = (const float*)d_in[21];
    const float* o_bv = (const float*)d_in[22], *o_bo = (const float*)d_in[23];
    const float* o_g  = (const float*)d_in[24], *o_b  = (const float*)d_in[25];
    const float* W1 = (const float*)d_in[26], *b1 = (const float*)d_in[27];
    const float* W2 = (const float*)d_in[28], *b2 = (const float*)d_in[29];
    const float* n3g = (const float*)d_in[30], *n3b = (const float*)d_in[31];
    float* out = (float*)d_out;

    __half *ln, *kvf, *kvo, *fsr, *osr, *Qh, *Kh, *Vh, *Koh, *Voh, *at, *h1, *WT;
    float *x, *pt, *mlp;
    cudaGetSymbolAddress((void**)&ln,  hb_ln);
    cudaGetSymbolAddress((void**)&kvf, hb_kvf);
    cudaGetSymbolAddress((void**)&kvo, hb_kvo);
    cudaGetSymbolAddress((void**)&fsr, hb_fsr);
    cudaGetSymbolAddress((void**)&osr, hb_osr);
    cudaGetSymbolAddress((void**)&Qh,  hb_Q);
    cudaGetSymbolAddress((void**)&Kh,  hb_K);
    cudaGetSymbolAddress((void**)&Vh,  hb_V);
    cudaGetSymbolAddress((void**)&Koh, hb_Ko);
    cudaGetSymbolAddress((void**)&Voh, hb_Vo);
    cudaGetSymbolAddress((void**)&at,  hb_at);
    cudaGetSymbolAddress((void**)&h1,  hb_h1);
    cudaGetSymbolAddress((void**)&WT,  hb_WT);
    cudaGetSymbolAddress((void**)&x,   g_x);
    cudaGetSymbolAddress((void**)&pt,  g_part);
    cudaGetSymbolAddress((void**)&mlp, g_ml);

    cudaFuncSetAttribute(tgemm_k<64 ,false,false,true >, cudaFuncAttributeMaxDynamicSharedMemorySize, GSMEM64);
    cudaFuncSetAttribute(tgemm_k<64 ,false,true ,false>, cudaFuncAttributeMaxDynamicSharedMemorySize, GSMEM64);
    cudaFuncSetAttribute(tgemm_k<128,false,false,true >, cudaFuncAttributeMaxDynamicSharedMemorySize, GSMEM128);
    cudaFuncSetAttribute(tgemm_k<128,true ,false,true >, cudaFuncAttributeMaxDynamicSharedMemorySize, GSMEM128);
    cudaFuncSetAttribute(fattn_k, cudaFuncAttributeMaxDynamicSharedMemorySize, ATTN_SMEM);

    if (!g_sA) {
        cudaStreamCreateWithFlags(&g_sA, cudaStreamNonBlocking);
        cudaStreamCreateWithFlags(&g_sB, cudaStreamNonBlocking);
        cudaEventCreateWithFlags(&g_evRoot, cudaEventDisableTiming);
        cudaEventCreateWithFlags(&g_evW,  cudaEventDisableTiming);
        cudaEventCreateWithFlags(&g_evKf, cudaEventDisableTiming);
        cudaEventCreateWithFlags(&g_evVf, cudaEventDisableTiming);
        cudaEventCreateWithFlags(&g_evKo, cudaEventDisableTiming);
        cudaEventCreateWithFlags(&g_evVo, cudaEventDisableTiming);
        cudaEventCreateWithFlags(&g_evA,  cudaEventDisableTiming);
    }
    cudaStream_t sA = g_sA, sB = g_sB;

    const float qscale = 0.125f * 1.4426950408889634f;
    dim3 g_q64(Dm / 64, MQ / 64);        // (8,32)  BN=64
    dim3 g_kv128(Dm / 128, MKV / 64);    // (4,128) BN=128
    dim3 g_ffn1(Ff / 128, MQ / 64);      // (16,32) BN=128
    dim3 g_attn(LQ / 64, NH, Bc * SPLIT);

    __half *rf_Wq = WT,               *rf_Wk = WT + 262144,
           *rf_Wv = WT + 2*262144,    *rf_Wo = WT + 3*262144,
           *ro_Wq = WT + 4*262144,    *ro_Wk = WT + 5*262144,
           *ro_Wv = WT + 6*262144,    *ro_Wo = WT + 7*262144,
           *rW1   = WT + 8*262144,    *rW2   = WT + 8*262144 + 1048576;

    TWTab tab;
    tab.s[0] = {f_Wq, rf_Wq, Dm, Dm, 256};  tab.s[1] = {f_Wk, rf_Wk, Dm, Dm, 256};
    tab.s[2] = {f_Wv, rf_Wv, Dm, Dm, 256};  tab.s[3] = {f_Wo, rf_Wo, Dm, Dm, 256};
    tab.s[4] = {o_Wq, ro_Wq, Dm, Dm, 256};  tab.s[5] = {o_Wk, ro_Wk, Dm, Dm, 256};
    tab.s[6] = {o_Wv, ro_Wv, Dm, Dm, 256};  tab.s[7] = {o_Wo, ro_Wo, Dm, Dm, 256};
    tab.s[8] = {W1, rW1, Dm, Ff, 1024};     tab.s[9] = {W2, rW2, Ff, Dm, 1024};

    // ---- fork side streams from the capture-origin stream FIRST ----
    cudaEventRecord(g_evRoot, 0);
    cudaStreamWaitEvent(sA, g_evRoot, 0);
    cudaStreamWaitEvent(sB, g_evRoot, 0);

    // ---- main stream: weights ----
    tWall_k<<<4096, dim3(32, 8)>>>(tab);
    cudaEventRecord(g_evW, 0);

    // ---- side stream A: kvf -> Kf ; kvo -> Ko ; passthrough copies ----
    prep_seg_k<<<4096, 256, 0, sA>>>(4, fs, fpe, os_, ope, out, fsr, osr, kvf, kvo);
    cudaStreamWaitEvent(sA, g_evW, 0);
    tgemm_k<128,false,false,true ><<<g_kv128, 128, GSMEM128, sA>>>(kvf, rf_Wk, f_bk, nullptr, Kh,  MKV, Dm, Dm, 1.f);
    cudaEventRecord(g_evKf, sA);
    prep_seg_k<<<4096, 256, 0, sA>>>(5, fs, fpe, os_, ope, out, fsr, osr, kvf, kvo);
    tgemm_k<128,false,false,true ><<<g_kv128, 128, GSMEM128, sA>>>(kvo, ro_Wk, o_bk, nullptr, Koh, MKV, Dm, Dm, 1.f);
    cudaEventRecord(g_evKo, sA);
    prep_seg_k<<<4096, 256, 0, sA>>>(0, fs, fpe, os_, ope, out, fsr, osr, kvf, kvo);
    prep_seg_k<<<4096, 256, 0, sA>>>(1, fs, fpe, os_, ope, out, fsr, osr, kvf, kvo);
    cudaEventRecord(g_evA, sA);

    // ---- side stream B: fsr -> Vf ; osr -> Vo ----
    prep_seg_k<<<4096, 256, 0, sB>>>(2, fs, fpe, os_, ope, out, fsr, osr, kvf, kvo);
    cudaStreamWaitEvent(sB, g_evW, 0);
    tgemm_k<128,false,false,true ><<<g_kv128, 128, GSMEM128, sB>>>(fsr, rf_Wv, f_bv, nullptr, Vh,  MKV, Dm, Dm, 1.f);
    cudaEventRecord(g_evVf, sB);
    prep_seg_k<<<4096, 256, 0, sB>>>(3, fs, fpe, os_, ope, out, fsr, osr, kvf, kvo);
    tgemm_k<128,false,false,true ><<<g_kv128, 128, GSMEM128, sB>>>(osr, ro_Wv, o_bv, nullptr, Voh, MKV, Dm, Dm, 1.f);
    cudaEventRecord(g_evVo, sB);

    // ---- main stream: critical chain ----
    ln_pe_k<<<MQ, 128>>>(hs, f_g, f_b, hpe, ln);
    tgemm_k<64 ,false,false,true ><<<g_q64, 128, GSMEM64>>>(ln, rf_Wq, f_bq, nullptr, Qh, MQ, Dm, Dm, qscale);
    cudaStreamWaitEvent(0, g_evKf, 0);
    cudaStreamWaitEvent(0, g_evVf, 0);
    fattn_k<<<g_attn, 64, ATTN_SMEM>>>(Qh, Kh, Vh, pt, mlp);
    comb_k<<<MQ, 128>>>(pt, mlp, at);
    tgemm_k<64 ,false,true ,false><<<g_q64, 128, GSMEM64>>>(at, rf_Wo, f_bo, hs, x, MQ, Dm, Dm, 1.f);

    ln_pe_k<<<MQ, 128>>>(x, o_g, o_b, hpe, ln);
    tgemm_k<64 ,false,false,true ><<<g_q64, 128, GSMEM64>>>(ln, ro_Wq, o_bq, nullptr, Qh, MQ, Dm, Dm, qscale);
    cudaStreamWaitEvent(0, g_evKo, 0);
    cudaStreamWaitEvent(0, g_evVo, 0);
    fattn_k<<<g_attn, 64, ATTN_SMEM>>>(Qh, Koh, Voh, pt, mlp);
    comb_k<<<MQ, 128>>>(pt, mlp, at);
    tgemm_k<64 ,false,true ,false><<<g_q64, 128, GSMEM64>>>(at, ro_Wo, o_bo, x, x, MQ, Dm, Dm, 1.f);

    ln_pe_k<<<MQ, 128>>>(x, n3g, n3b, nullptr, ln);
    tgemm_k<128,true ,false,true ><<<g_ffn1, 128, GSMEM128>>>(ln, rW1, b1, nullptr, h1, MQ, Ff, Dm, 1.f);
    cudaStreamWaitEvent(0, g_evA, 0);   // rejoin stream A (copies) before final node
    tgemm_k<64 ,false,true ,false><<<g_q64,  128, GSMEM64 >>>(h1, rW2, b2, x, out, MQ, Dm, Ff, 1.f);
}

// round 16
// speedup vs baseline: 1.1002x; 1.1002x over previous
#include <cuda_runtime.h>
#include <cuda_fp16.h>
#include <cstdint>

// ---------------- problem dims (fixed) ----------------
#define Bc   2
#define LQ   1024
#define LKV  4096
#define Dm   512
#define NH   8
#define DHd  64
#define Ff   2048
#define MQ   (Bc*LQ)    // 2048
#define MKV  (Bc*LKV)   // 8192
#define SPLIT 2
#define TKV  (LKV / 64 / SPLIT)   // 32

// ---------------- scratch (device globals) ----------------
__device__ __half hb_ln [MQ*Dm];
__device__ __half hb_kvf[MKV*Dm];
__device__ __half hb_kvo[MKV*Dm];
__device__ __half hb_fsr[MKV*Dm];
__device__ __half hb_osr[MKV*Dm];
__device__ __half hb_Q  [MQ*Dm];
__device__ __half hb_K  [MKV*Dm];
__device__ __half hb_V  [MKV*Dm];
__device__ __half hb_Ko [MKV*Dm];
__device__ __half hb_Vo [MKV*Dm];
__device__ __half hb_at [MQ*Dm];
__device__ __half hb_h1 [MQ*Ff];
__device__ __half hb_WT [8*262144 + 2*1048576];
__device__ float  g_x   [MQ*Dm];
__device__ float  g_part[SPLIT*MQ*Dm];
__device__ float  g_ml  [SPLIT*MQ*NH*2];

// ---------------- helpers ----------------
__device__ __forceinline__ uint32_t packh2(float a, float b) {
    __half2 h = __floats2half2_rn(a, b);
    return *(uint32_t*)&h;
}
__device__ __forceinline__ float ex2(float x) {
    float y; asm("ex2.approx.f32 %0, %1;" : "=f"(y) : "f"(x)); return y;
}
__device__ __forceinline__ void cpa16(uint32_t dst, const void* src) {
    asm volatile("cp.async.cg.shared.global [%0], [%1], 16;" :: "r"(dst), "l"(src));
}
__device__ __forceinline__ void cpa_commit() {
    asm volatile("cp.async.commit_group;" ::: "memory");
}
template <int N> __device__ __forceinline__ void cpa_wait() {
    asm volatile("cp.async.wait_group %0;" :: "n"(N) : "memory");
}
__device__ __forceinline__ void mma_f16(float c[4], const uint32_t a[4],
                                        uint32_t b0, uint32_t b1) {
    asm("mma.sync.aligned.m16n8k16.row.col.f32.f16.f16.f32 "
        "{%0,%1,%2,%3},{%4,%5,%6,%7},{%8,%9},{%0,%1,%2,%3};"
        : "+f"(c[0]), "+f"(c[1]), "+f"(c[2]), "+f"(c[3])
        : "r"(a[0]), "r"(a[1]), "r"(a[2]), "r"(a[3]), "r"(b0), "r"(b1));
}
__device__ __forceinline__ void ldsm_x4(uint32_t& r0, uint32_t& r1, uint32_t& r2,
                                        uint32_t& r3, uint32_t addr) {
    asm volatile("ldmatrix.sync.aligned.m8n8.x4.shared.b16 {%0,%1,%2,%3},[%4];"
        : "=r"(r0), "=r"(r1), "=r"(r2), "=r"(r3) : "r"(addr));
}
__device__ __forceinline__ void ldsm_x4_t(uint32_t& r0, uint32_t& r1, uint32_t& r2,
                                          uint32_t& r3, uint32_t addr) {
    asm volatile("ldmatrix.sync.aligned.m8n8.x4.trans.shared.b16 {%0,%1,%2,%3},[%4];"
        : "=r"(r0), "=r"(r1), "=r"(r2), "=r"(r3) : "r"(addr));
}

// ---------------- per-segment prep ----------------
// seg: 0 copy fs->out, 1 copy os->out, 2 fs->fsr(h), 3 os->osr(h),
//      4 fs+fpe->kvf(h), 5 os+ope->kvo(h)
__global__ void prep_seg_k(int seg,
                           const float* __restrict__ fs, const float* __restrict__ fpe,
                           const float* __restrict__ os_, const float* __restrict__ ope,
                           float* __restrict__ out, __half* __restrict__ fsr,
                           __half* __restrict__ osr, __half* __restrict__ kvf,
                           __half* __restrict__ kvo) {
    const int i = blockIdx.x * 256 + threadIdx.x;
    switch (seg) {
    case 0: ((float4*)(out + (size_t)MQ * Dm))[i] = ((const float4*)fs)[i]; break;
    case 1: ((float4*)(out + (size_t)MQ * Dm + (size_t)MKV * Dm))[i] = ((const float4*)os_)[i]; break;
    case 2: { float4 v = ((const float4*)fs)[i];
              ((uint2*)fsr)[i] = make_uint2(packh2(v.x, v.y), packh2(v.z, v.w)); break; }
    case 3: { float4 v = ((const float4*)os_)[i];
              ((uint2*)osr)[i] = make_uint2(packh2(v.x, v.y), packh2(v.z, v.w)); break; }
    case 4: { float4 a = ((const float4*)fs)[i], b = ((const float4*)fpe)[i];
              ((uint2*)kvf)[i] = make_uint2(packh2(a.x + b.x, a.y + b.y),
                                            packh2(a.z + b.z, a.w + b.w)); break; }
    default:{ float4 a = ((const float4*)os_)[i], b = ((const float4*)ope)[i];
              ((uint2*)kvo)[i] = make_uint2(packh2(a.x + b.x, a.y + b.y),
                                            packh2(a.z + b.z, a.w + b.w)); break; }
    }
}

// ---------------- fused weight transpose ----------------
struct TWSeg { const float* src; __half* dst; int K; int N; int tiles; };
struct TWTab { TWSeg s[10]; };
__global__ void tWall_k(TWTab tab) {
    __shared__ float t[32][33];
    int tI = blockIdx.x, j = 0;
#pragma unroll
    for (int q = 0; q < 9; q++) if (tI >= tab.s[j].tiles) { tI -= tab.s[j].tiles; j++; }
    const float* W = tab.s[j].src;
    __half* WT = tab.s[j].dst;
    const int K = tab.s[j].K, N = tab.s[j].N;
    const int ntx = N >> 5;
    const int n0 = (tI % ntx) * 32, k0 = (tI / ntx) * 32;
    const int tx = threadIdx.x, ty = threadIdx.y;
#pragma unroll
    for (int r = 0; r < 32; r += 8)
        t[ty + r][tx] = W[(size_t)(k0 + ty + r) * N + n0 + tx];
    __syncthreads();
#pragma unroll
    for (int r = 0; r < 32; r += 8)
        WT[(size_t)(n0 + ty + r) * K + k0 + tx] = __float2half_rn(t[tx][ty + r]);
}

// ---------------- layernorm (+ optional pe), half output ----------------
__global__ void ln_pe_k(const float* __restrict__ x, const float* __restrict__ g,
                        const float* __restrict__ b, const float* __restrict__ pe,
                        __half* __restrict__ out) {
    __shared__ float red[8];
    const int row = blockIdx.x, tid = threadIdx.x;
    const float* xr = x + (size_t)row * Dm;
    float4 xv = *(const float4*)&xr[tid * 4];
    float sum = xv.x + xv.y + xv.z + xv.w;
    float sq  = xv.x*xv.x + xv.y*xv.y + xv.z*xv.z + xv.w*xv.w;
#pragma unroll
    for (int off = 16; off > 0; off >>= 1) {
        sum += __shfl_xor_sync(0xffffffffu, sum, off);
        sq  += __shfl_xor_sync(0xffffffffu, sq,  off);
    }
    if ((tid & 31) == 0) { red[tid >> 5] = sum; red[4 + (tid >> 5)] = sq; }
    __syncthreads();
    sum = red[0] + red[1] + red[2] + red[3];
    sq  = red[4] + red[5] + red[6] + red[7];
    float mu   = sum * (1.0f / Dm);
    float var  = sq * (1.0f / Dm) - mu * mu;
    float rstd = rsqrtf(var + 1e-6f);
    float4 gv = *(const float4*)&g[tid * 4];
    float4 bv = *(const float4*)&b[tid * 4];
    float4 r;
    r.x = (xv.x - mu) * rstd * gv.x + bv.x;
    r.y = (xv.y - mu) * rstd * gv.y + bv.y;
    r.z = (xv.z - mu) * rstd * gv.z + bv.z;
    r.w = (xv.w - mu) * rstd * gv.w + bv.w;
    if (pe) {
        const float4 pv = *(const float4*)&pe[(size_t)row * Dm + tid * 4];
        r.x += pv.x; r.y += pv.y; r.z += pv.z; r.w += pv.w;
    }
    *(uint2*)&out[(size_t)row * Dm + tid * 4] = make_uint2(packh2(r.x, r.y), packh2(r.z, r.w));
}

// ---------------- fp16 GEMM, cp.async 3-stage, ldmatrix, templated BN ----------------
#define APITCH 40

template <int BN, bool RELU, bool RES, bool HOUT>
__global__ void __launch_bounds__(128) tgemm_k(
    const __half* __restrict__ A, const __half* __restrict__ WT,
    const float* __restrict__ bias, const float* __restrict__ res,
    void* __restrict__ C, int M, int N, int K, float scale)
{
    constexpr int NI   = BN / 16;
    constexpr int BP   = BN / 32;
    constexpr int GST  = (64 + BN) * APITCH * 2;
    extern __shared__ __half smh[];
    const int tid = threadIdx.x, lane = tid & 31, w = tid >> 5;
    const int wm = w >> 1, wn = w & 1;
    const int g = lane >> 2, qd = lane & 3;
    const int m0 = blockIdx.y * 64, n0 = blockIdx.x * BN;
    const uint32_t sbase = (uint32_t)__cvta_generic_to_shared(smh);

    const int fra = tid >> 1, fca = (tid & 1) * 16;
    const __half* aSrc = A + (size_t)(m0 + fra) * K + fca;
    const uint32_t aDst = sbase + (fra * APITCH + fca) * 2;
    const int frb = (BP == 2) ? (tid >> 1) : tid;
    const int fcb = (BP == 2) ? ((tid & 1) * 16) : 0;
    const __half* bSrc = WT + (size_t)(n0 + frb) * K + fcb;
    const uint32_t bDst = sbase + ((64 + frb) * APITCH + fcb) * 2;

    const int L = lane;
    const uint32_t aOff = ((wm * 32 + ((L >> 3) & 1) * 8 + (L & 7)) * APITCH
                           + (L >> 4) * 8) * 2;
    const uint32_t bOff = ((64 + wn * (BN / 2) + (L >> 4) * 8 + (L & 7)) * APITCH
                           + ((L >> 3) & 1) * 8) * 2;

    const int KT = K >> 5;
#pragma unroll
    for (int pre = 0; pre < 2; pre++) {
        const __half* sa = aSrc + pre * 32;
        const __half* sb = bSrc + pre * 32;
        uint32_t da = aDst + pre * GST, db = bDst + pre * GST;
        cpa16(da, sa); cpa16(da + 16, sa + 8);
#pragma unroll
        for (int i = 0; i < ((BP == 2) ? 2 : 4); i++)
            cpa16(db + i * 16, sb + i * 8);
        cpa_commit();
    }

    float acc[2][NI][4];
#pragma unroll
    for (int mi = 0; mi < 2; mi++)
#pragma unroll
        for (int ni = 0; ni < NI; ni++)
#pragma unroll
            for (int e = 0; e < 4; e++) acc[mi][ni][e] = 0.f;

    for (int kt = 0; kt < KT; kt++) {
        cpa_wait<1>();
        __syncthreads();
        if (kt + 2 < KT) {
            int s2 = (kt + 2) % 3;
            const __half* sa = aSrc + (kt + 2) * 32;
            const __half* sb = bSrc + (kt + 2) * 32;
            uint32_t da = aDst + s2 * GST, db = bDst + s2 * GST;
            cpa16(da, sa); cpa16(da + 16, sa + 8);
#pragma unroll
            for (int i = 0; i < ((BP == 2) ? 2 : 4); i++)
                cpa16(db + i * 16, sb + i * 8);
        }
        cpa_commit();
        const uint32_t st = sbase + (kt % 3) * GST;
#pragma unroll
        for (int ks = 0; ks < 2; ks++) {
            uint32_t af[2][4], bf[NI][2];
#pragma unroll
            for (int mi = 0; mi < 2; mi++)
                ldsm_x4(af[mi][0], af[mi][1], af[mi][2], af[mi][3],
                        st + aOff + (mi * 16 * APITCH + ks * 16) * 2);
#pragma unroll
            for (int p = 0; p < BP; p++) {
                uint32_t r0, r1, r2, r3;
                ldsm_x4(r0, r1, r2, r3, st + bOff + (p * 16 * APITCH + ks * 16) * 2);
                bf[2*p][0] = r0; bf[2*p][1] = r1;
                bf[2*p+1][0] = r2; bf[2*p+1][1] = r3;
            }
#pragma unroll
            for (int mi = 0; mi < 2; mi++)
#pragma unroll
                for (int ni = 0; ni < NI; ni++)
                    mma_f16(acc[mi][ni], af[mi], bf[ni][0], bf[ni][1]);
        }
    }

#pragma unroll
    for (int mi = 0; mi < 2; mi++) {
        int mrow = m0 + wm * 32 + mi * 16 + g;
#pragma unroll
        for (int ni = 0; ni < NI; ni++) {
            int ncol = n0 + wn * (BN / 2) + ni * 8 + 2 * qd;
            float2 bv = *(const float2*)&bias[ncol];
#pragma unroll
            for (int hh = 0; hh < 2; hh++) {
                size_t m = (size_t)(mrow + hh * 8);
                float vx = acc[mi][ni][hh * 2 + 0] + bv.x;
                float vy = acc[mi][ni][hh * 2 + 1] + bv.y;
                if (RELU) { vx = fmaxf(vx, 0.f); vy = fmaxf(vy, 0.f); }
                vx *= scale; vy *= scale;
                if (HOUT) {
                    *(__half2*)((__half*)C + m * N + ncol) = __floats2half2_rn(vx, vy);
                } else {
                    if (RES) {
                        float2 rv = *(const float2*)&res[m * N + ncol];
                        vx += rv.x; vy += rv.y;
                    }
                    *(float2*)((float*)C + m * N + ncol) = make_float2(vx, vy);
                }
            }
        }
    }
}

// ---------------- fp16 flash attention, kv-split, double-buffered ----------------
#define FPITCH 72
#define QB  (64 * FPITCH * 2)
#define ATTN_SMEM (5 * QB)

__global__ void __launch_bounds__(64) fattn_k(
    const __half* __restrict__ Qm, const __half* __restrict__ Km,
    const __half* __restrict__ Vm, float* __restrict__ part, float* __restrict__ ml)
{
    extern __shared__ __half smf[];
    const uint32_t sbase = (uint32_t)__cvta_generic_to_shared(smf);
    const uint32_t sQ = sbase;

    const int tid = threadIdx.x;
    const int lane = tid & 31, w = tid >> 5;
    const int g = lane >> 2, qd = lane & 3;
    const int bb = blockIdx.z / SPLIT, sp = blockIdx.z % SPLIT;
    const int hh = blockIdx.y, qt = blockIdx.x;
    const size_t qrow0 = (size_t)bb * LQ + qt * 64;
    const int hoff = hh * DHd;
    const int mb = w * 32;
    const int L = lane;

    const int frr = tid >> 3, fcc = (tid & 7);
#pragma unroll
    for (int it = 0; it < 8; it++) {
        int r = frr + it * 8;
        cpa16(sQ + (r * FPITCH + fcc * 8) * 2, &Qm[(qrow0 + r) * Dm + hoff + fcc * 8]);
    }
    size_t kvb = (size_t)bb * LKV + (size_t)sp * TKV * 64;
#pragma unroll
    for (int it = 0; it < 8; it++) {
        int r = frr + it * 8;
        size_t gi = (kvb + r) * Dm + hoff + fcc * 8;
        cpa16(sQ + QB + (r * FPITCH + fcc * 8) * 2,     &Km[gi]);
        cpa16(sQ + 2 * QB + (r * FPITCH + fcc * 8) * 2, &Vm[gi]);
    }
    cpa_commit();
#pragma unroll
    for (int it = 0; it < 8; it++) {
        int r = frr + it * 8;
        size_t gi = (kvb + 64 + r) * Dm + hoff + fcc * 8;
        cpa16(sQ + 3 * QB + (r * FPITCH + fcc * 8) * 2, &Km[gi]);
        cpa16(sQ + 4 * QB + (r * FPITCH + fcc * 8) * 2, &Vm[gi]);
    }
    cpa_commit();

    const uint32_t qOff = ((mb + ((L >> 3) & 1) * 8 + (L & 7)) * FPITCH + (L >> 4) * 8) * 2;
    const uint32_t kOff = (((L >> 4) * 8 + (L & 7)) * FPITCH + ((L >> 3) & 1) * 8) * 2;
    const uint32_t vOff = ((L & 15) * FPITCH + (L >> 4) * 8) * 2;

    uint32_t aq[2][4][4];
    float o[2][8][4] = {};
    float mr[2][2] = {{-1e30f, -1e30f}, {-1e30f, -1e30f}};
    float lr[2][2] = {{0.f, 0.f}, {0.f, 0.f}};

    for (int t = 0; t < TKV; t++) {
        cpa_wait<1>();
        __syncthreads();
        if (t == 0) {
#pragma unroll
            for (int mi = 0; mi < 2; mi++)
#pragma unroll
                for (int ks = 0; ks < 4; ks++)
                    ldsm_x4(aq[mi][ks][0], aq[mi][ks][1], aq[mi][ks][2], aq[mi][ks][3],
                            sQ + qOff + (mi * 16 * FPITCH + ks * 16) * 2);
        }
        const uint32_t sK = sQ + QB + (t & 1) * 2 * QB;
        const uint32_t sV = sK + QB;

        float s[2][8][4] = {};
#pragma unroll
        for (int ks = 0; ks < 4; ks++) {
            uint32_t kb[8][2];
#pragma unroll
            for (int p = 0; p < 4; p++) {
                uint32_t r0, r1, r2, r3;
                ldsm_x4(r0, r1, r2, r3, sK + kOff + (p * 16 * FPITCH + ks * 16) * 2);
                kb[2*p][0] = r0; kb[2*p][1] = r1;
                kb[2*p+1][0] = r2; kb[2*p+1][1] = r3;
            }
#pragma unroll
            for (int mi = 0; mi < 2; mi++)
#pragma unroll
                for (int ni = 0; ni < 8; ni++)
                    mma_f16(s[mi][ni], aq[mi][ks], kb[ni][0], kb[ni][1]);
        }

        float es[2][2];
#pragma unroll
        for (int mi = 0; mi < 2; mi++) {
            float mx0 = -1e30f, mx1 = -1e30f;
#pragma unroll
            for (int ni = 0; ni < 8; ni++) {
                mx0 = fmaxf(mx0, fmaxf(s[mi][ni][0], s[mi][ni][1]));
                mx1 = fmaxf(mx1, fmaxf(s[mi][ni][2], s[mi][ni][3]));
            }
            mx0 = fmaxf(mx0, __shfl_xor_sync(~0u, mx0, 1));
            mx0 = fmaxf(mx0, __shfl_xor_sync(~0u, mx0, 2));
            mx1 = fmaxf(mx1, __shfl_xor_sync(~0u, mx1, 1));
            mx1 = fmaxf(mx1, __shfl_xor_sync(~0u, mx1, 2));
            float mn0 = fmaxf(mr[mi][0], mx0), mn1 = fmaxf(mr[mi][1], mx1);
            float sum0 = 0.f, sum1 = 0.f;
#pragma unroll
            for (int ni = 0; ni < 8; ni++) {
                s[mi][ni][0] = ex2(s[mi][ni][0] - mn0);
                s[mi][ni][1] = ex2(s[mi][ni][1] - mn0);
                s[mi][ni][2] = ex2(s[mi][ni][2] - mn1);
                s[mi][ni][3] = ex2(s[mi][ni][3] - mn1);
                sum0 += s[mi][ni][0] + s[mi][ni][1];
                sum1 += s[mi][ni][2] + s[mi][ni][3];
            }
            sum0 += __shfl_xor_sync(~0u, sum0, 1); sum0 += __shfl_xor_sync(~0u, sum0, 2);
            sum1 += __shfl_xor_sync(~0u, sum1, 1); sum1 += __shfl_xor_sync(~0u, sum1, 2);
            es[mi][0] = ex2(mr[mi][0] - mn0); es[mi][1] = ex2(mr[mi][1] - mn1);
            mr[mi][0] = mn0; mr[mi][1] = mn1;
            lr[mi][0] = lr[mi][0] * es[mi][0] + sum0;
            lr[mi][1] = lr[mi][1] * es[mi][1] + sum1;
#pragma unroll
            for (int ni = 0; ni < 8; ni++) {
                o[mi][ni][0] *= es[mi][0]; o[mi][ni][1] *= es[mi][0];
                o[mi][ni][2] *= es[mi][1]; o[mi][ni][3] *= es[mi][1];
            }
        }

#pragma unroll
        for (int ks = 0; ks < 4; ks++) {
            uint32_t vb[8][2];
#pragma unroll
            for (int j = 0; j < 4; j++) {
                uint32_t r0, r1, r2, r3;
                ldsm_x4_t(r0, r1, r2, r3, sV + vOff + (ks * 16 * FPITCH + j * 16) * 2);
                vb[2*j][0] = r0; vb[2*j][1] = r1;
                vb[2*j+1][0] = r2; vb[2*j+1][1] = r3;
            }
            uint32_t ap[2][4];
#pragma unroll
            for (int mi = 0; mi < 2; mi++) {
                ap[mi][0] = packh2(s[mi][2*ks][0],   s[mi][2*ks][1]);
                ap[mi][1] = packh2(s[mi][2*ks][2],   s[mi][2*ks][3]);
                ap[mi][2] = packh2(s[mi][2*ks+1][0], s[mi][2*ks+1][1]);
                ap[mi][3] = packh2(s[mi][2*ks+1][2], s[mi][2*ks+1][3]);
            }
#pragma unroll
            for (int mi = 0; mi < 2; mi++)
#pragma unroll
                for (int ni = 0; ni < 8; ni++)
                    mma_f16(o[mi][ni], ap[mi], vb[ni][0], vb[ni][1]);
        }

        __syncthreads();
        if (t + 2 < TKV) {
            size_t kv0 = kvb + (size_t)(t + 2) * 64;
            uint32_t dK = sQ + QB + (t & 1) * 2 * QB;
#pragma unroll
            for (int it = 0; it < 8; it++) {
                int r = frr + it * 8;
                size_t gi = (kv0 + r) * Dm + hoff + fcc * 8;
                cpa16(dK + (r * FPITCH + fcc * 8) * 2,      &Km[gi]);
                cpa16(dK + QB + (r * FPITCH + fcc * 8) * 2, &Vm[gi]);
            }
        }
        cpa_commit();
    }

#pragma unroll
    for (int mi = 0; mi < 2; mi++) {
        int rloc = mb + mi * 16 + g;
#pragma unroll
        for (int ni = 0; ni < 8; ni++) {
            int ncol = hoff + ni * 8 + 2 * qd;
            *(float2*)&part[((size_t)sp * MQ + qrow0 + rloc) * Dm + ncol] =
                make_float2(o[mi][ni][0], o[mi][ni][1]);
            *(float2*)&part[((size_t)sp * MQ + qrow0 + rloc + 8) * Dm + ncol] =
                make_float2(o[mi][ni][2], o[mi][ni][3]);
        }
        if (qd == 0) {
            size_t b0 = (((size_t)sp * MQ + qrow0 + rloc) * NH + hh) * 2;
            ml[b0] = mr[mi][0]; ml[b0 + 1] = lr[mi][0];
            size_t b1 = (((size_t)sp * MQ + qrow0 + rloc + 8) * NH + hh) * 2;
            ml[b1] = mr[mi][1]; ml[b1 + 1] = lr[mi][1];
        }
    }
}

// ---------------- split combine (half output) ----------------
__global__ void comb_k(const float* __restrict__ part, const float* __restrict__ ml,
                       __half* __restrict__ out) {
    int row = blockIdx.x, tid = threadIdx.x;
    int c = tid * 4, h = c >> 6;
    float m[SPLIT], l[SPLIT];
#pragma unroll
    for (int sp = 0; sp < SPLIT; sp++) {
        const float* p = &ml[(((size_t)sp * MQ + row) * NH + h) * 2];
        m[sp] = p[0]; l[sp] = p[1];
    }
    float M = m[0];
#pragma unroll
    for (int sp = 1; sp < SPLIT; sp++) M = fmaxf(M, m[sp]);
    float s[SPLIT], Lh = 0.f;
#pragma unroll
    for (int sp = 0; sp < SPLIT; sp++) { s[sp] = ex2(m[sp] - M); Lh += l[sp] * s[sp]; }
    float inv = 1.f / Lh;
    float4 a = make_float4(0.f, 0.f, 0.f, 0.f);
#pragma unroll
    for (int sp = 0; sp < SPLIT; sp++) {
        float4 v = *(const float4*)&part[((size_t)sp * MQ + row) * Dm + c];
        a.x += v.x * s[sp]; a.y += v.y * s[sp];
        a.z += v.z * s[sp]; a.w += v.w * s[sp];
    }
    *(uint2*)&out[(size_t)row * Dm + c] =
        make_uint2(packh2(a.x * inv, a.y * inv), packh2(a.z * inv, a.w * inv));
}

// ---------------- host ----------------
#define GSMEM64  (3 * (64 + 64)  * APITCH * 2)
#define GSMEM128 (3 * (64 + 128) * APITCH * 2)

static cudaStream_t g_sA = nullptr, g_sB = nullptr;
static cudaEvent_t g_evRoot, g_evW, g_evKf, g_evVf, g_evKo, g_evVo, g_evB;

extern "C" void kernel_launch(void* const* d_in, const int* in_sizes, int n_in,
                              void* d_out, int out_size) {
    const float* hs  = (const float*)d_in[0];
    const float* hpe = (const float*)d_in[1];
    const float* fs  = (const float*)d_in[2];
    const float* fpe = (const float*)d_in[3];
    const float* os_ = (const float*)d_in[4];
    const float* ope = (const float*)d_in[5];
    const float* f_Wq = (const float*)d_in[6],  *f_Wk = (const float*)d_in[7];
    const float* f_Wv = (const float*)d_in[8],  *f_Wo = (const float*)d_in[9];
    const float* f_bq = (const float*)d_in[10], *f_bk = (const float*)d_in[11];
    const float* f_bv = (const float*)d_in[12], *f_bo = (const float*)d_in[13];
    const float* f_g  = (const float*)d_in[14], *f_b  = (const float*)d_in[15];
    const float* o_Wq = (const float*)d_in[16], *o_Wk = (const float*)d_in[17];
    const float* o_Wv = (const float*)d_in[18], *o_Wo = (const float*)d_in[19];
    const float* o_bq = (const float*)d_in[20], *o_bk = (const float*)d_in[21];
    const float* o_bv = (const float*)d_in[22], *o_bo = (const float*)d_in[23];
    const float* o_g  = (const float*)d_in[24], *o_b  = (const float*)d_in[25];
    const float* W1 = (const float*)d_in[26], *b1 = (const float*)d_in[27];
    const float* W2 = (const float*)d_in[28], *b2 = (const float*)d_in[29];
    const float* n3g = (const float*)d_in[30], *n3b = (const float*)d_in[31];
    float* out = (float*)d_out;

    __half *ln, *kvf, *kvo, *fsr, *osr, *Qh, *Kh, *Vh, *Koh, *Voh, *at, *h1, *WT;
    float *x, *pt, *mlp;
    cudaGetSymbolAddress((void**)&ln,  hb_ln);
    cudaGetSymbolAddress((void**)&kvf, hb_kvf);
    cudaGetSymbolAddress((void**)&kvo, hb_kvo);
    cudaGetSymbolAddress((void**)&fsr, hb_fsr);
    cudaGetSymbolAddress((void**)&osr, hb_osr);
    cudaGetSymbolAddress((void**)&Qh,  hb_Q);
    cudaGetSymbolAddress((void**)&Kh,  hb_K);
    cudaGetSymbolAddress((void**)&Vh,  hb_V);
    cudaGetSymbolAddress((void**)&Koh, hb_Ko);
    cudaGetSymbolAddress((void**)&Voh, hb_Vo);
    cudaGetSymbolAddress((void**)&at,  hb_at);
    cudaGetSymbolAddress((void**)&h1,  hb_h1);
    cudaGetSymbolAddress((void**)&WT,  hb_WT);
    cudaGetSymbolAddress((void**)&x,   g_x);
    cudaGetSymbolAddress((void**)&pt,  g_part);
    cudaGetSymbolAddress((void**)&mlp, g_ml);

    cudaFuncSetAttribute(tgemm_k<64 ,false,false,true >, cudaFuncAttributeMaxDynamicSharedMemorySize, GSMEM64);
    cudaFuncSetAttribute(tgemm_k<64 ,false,true ,false>, cudaFuncAttributeMaxDynamicSharedMemorySize, GSMEM64);
    cudaFuncSetAttribute(tgemm_k<128,false,false,true >, cudaFuncAttributeMaxDynamicSharedMemorySize, GSMEM128);
    cudaFuncSetAttribute(tgemm_k<128,true ,false,true >, cudaFuncAttributeMaxDynamicSharedMemorySize, GSMEM128);
    cudaFuncSetAttribute(fattn_k, cudaFuncAttributeMaxDynamicSharedMemorySize, ATTN_SMEM);

    if (!g_sA) {
        cudaStreamCreateWithFlags(&g_sA, cudaStreamNonBlocking);
        cudaStreamCreateWithFlags(&g_sB, cudaStreamNonBlocking);
        cudaEventCreateWithFlags(&g_evRoot, cudaEventDisableTiming);
        cudaEventCreateWithFlags(&g_evW,  cudaEventDisableTiming);
        cudaEventCreateWithFlags(&g_evKf, cudaEventDisableTiming);
        cudaEventCreateWithFlags(&g_evVf, cudaEventDisableTiming);
        cudaEventCreateWithFlags(&g_evKo, cudaEventDisableTiming);
        cudaEventCreateWithFlags(&g_evVo, cudaEventDisableTiming);
        cudaEventCreateWithFlags(&g_evB,  cudaEventDisableTiming);
    }
    cudaStream_t sA = g_sA, sB = g_sB;

    const float qscale = 0.125f * 1.4426950408889634f;
    dim3 g_q64(Dm / 64, MQ / 64);        // (8,32)  BN=64
    dim3 g_kv128(Dm / 128, MKV / 64);    // (4,128) BN=128
    dim3 g_ffn1(Ff / 128, MQ / 64);      // (16,32) BN=128
    dim3 g_attn(LQ / 64, NH, Bc * SPLIT);

    __half *rf_Wq = WT,               *rf_Wk = WT + 262144,
           *rf_Wv = WT + 2*262144,    *rf_Wo = WT + 3*262144,
           *ro_Wq = WT + 4*262144,    *ro_Wk = WT + 5*262144,
           *ro_Wv = WT + 6*262144,    *ro_Wo = WT + 7*262144,
           *rW1   = WT + 8*262144,    *rW2   = WT + 8*262144 + 1048576;

    TWTab tab;
    tab.s[0] = {f_Wq, rf_Wq, Dm, Dm, 256};  tab.s[1] = {f_Wk, rf_Wk, Dm, Dm, 256};
    tab.s[2] = {f_Wv, rf_Wv, Dm, Dm, 256};  tab.s[3] = {f_Wo, rf_Wo, Dm, Dm, 256};
    tab.s[4] = {o_Wq, ro_Wq, Dm, Dm, 256};  tab.s[5] = {o_Wk, ro_Wk, Dm, Dm, 256};
    tab.s[6] = {o_Wv, ro_Wv, Dm, Dm, 256};  tab.s[7] = {o_Wo, ro_Wo, Dm, Dm, 256};
    tab.s[8] = {W1, rW1, Dm, Ff, 1024};     tab.s[9] = {W2, rW2, Ff, Dm, 1024};

    // ---- fork side streams from the capture-origin stream FIRST ----
    cudaEventRecord(g_evRoot, 0);
    cudaStreamWaitEvent(sA, g_evRoot, 0);
    cudaStreamWaitEvent(sB, g_evRoot, 0);

    // ---- main stream: weights ----
    tWall_k<<<4096, dim3(32, 8)>>>(tab);
    cudaEventRecord(g_evW, 0);

    // ---- side stream A: kvf -> Kf ; kvo -> Ko ----
    prep_seg_k<<<4096, 256, 0, sA>>>(4, fs, fpe, os_, ope, out, fsr, osr, kvf, kvo);
    cudaStreamWaitEvent(sA, g_evW, 0);
    tgemm_k<128,false,false,true ><<<g_kv128, 128, GSMEM128, sA>>>(kvf, rf_Wk, f_bk, nullptr, Kh,  MKV, Dm, Dm, 1.f);
    cudaEventRecord(g_evKf, sA);
    prep_seg_k<<<4096, 256, 0, sA>>>(5, fs, fpe, os_, ope, out, fsr, osr, kvf, kvo);
    tgemm_k<128,false,false,true ><<<g_kv128, 128, GSMEM128, sA>>>(kvo, ro_Wk, o_bk, nullptr, Koh, MKV, Dm, Dm, 1.f);
    cudaEventRecord(g_evKo, sA);

    // ---- side stream B: fsr -> Vf ; osr -> Vo ; passthrough copies last ----
    prep_seg_k<<<4096, 256, 0, sB>>>(2, fs, fpe, os_, ope, out, fsr, osr, kvf, kvo);
    cudaStreamWaitEvent(sB, g_evW, 0);
    tgemm_k<128,false,false,true ><<<g_kv128, 128, GSMEM128, sB>>>(fsr, rf_Wv, f_bv, nullptr, Vh,  MKV, Dm, Dm, 1.f);
    cudaEventRecord(g_evVf, sB);
    prep_seg_k<<<4096, 256, 0, sB>>>(3, fs, fpe, os_, ope, out, fsr, osr, kvf, kvo);
    tgemm_k<128,false,false,true ><<<g_kv128, 128, GSMEM128, sB>>>(osr, ro_Wv, o_bv, nullptr, Voh, MKV, Dm, Dm, 1.f);
    cudaEventRecord(g_evVo, sB);
    prep_seg_k<<<4096, 256, 0, sB>>>(0, fs, fpe, os_, ope, out, fsr, osr, kvf, kvo);
    prep_seg_k<<<4096, 256, 0, sB>>>(1, fs, fpe, os_, ope, out, fsr, osr, kvf, kvo);
    cudaEventRecord(g_evB, sB);

    // ---- main stream: critical chain ----
    ln_pe_k<<<MQ, 128>>>(hs, f_g, f_b, hpe, ln);
    tgemm_k<64 ,false,false,true ><<<g_q64, 128, GSMEM64>>>(ln, rf_Wq, f_bq, nullptr, Qh, MQ, Dm, Dm, qscale);
    cudaStreamWaitEvent(0, g_evKf, 0);
    cudaStreamWaitEvent(0, g_evVf, 0);
    fattn_k<<<g_attn, 64, ATTN_SMEM>>>(Qh, Kh, Vh, pt, mlp);
    comb_k<<<MQ, 128>>>(pt, mlp, at);
    tgemm_k<64 ,false,true ,false><<<g_q64, 128, GSMEM64>>>(at, rf_Wo, f_bo, hs, x, MQ, Dm, Dm, 1.f);

    ln_pe_k<<<MQ, 128>>>(x, o_g, o_b, hpe, ln);
    tgemm_k<64 ,false,false,true ><<<g_q64, 128, GSMEM64>>>(ln, ro_Wq, o_bq, nullptr, Qh, MQ, Dm, Dm, qscale);
    cudaStreamWaitEvent(0, g_evKo, 0);
    cudaStreamWaitEvent(0, g_evVo, 0);
    fattn_k<<<g_attn, 64, ATTN_SMEM>>>(Qh, Koh, Voh, pt, mlp);
    comb_k<<<MQ, 128>>>(pt, mlp, at);
    tgemm_k<64 ,false,true ,false><<<g_q64, 128, GSMEM64>>>(at, ro_Wo, o_bo, x, x, MQ, Dm, Dm, 1.f);

    ln_pe_k<<<MQ, 128>>>(x, n3g, n3b, nullptr, ln);
    tgemm_k<128,true ,false,true ><<<g_ffn1, 128, GSMEM128>>>(ln, rW1, b1, nullptr, h1, MQ, Ff, Dm, 1.f);
    cudaStreamWaitEvent(0, g_evB, 0);   // rejoin stream B (copies) before final node
    tgemm_k<64 ,false,true ,false><<<g_q64,  128, GSMEM64 >>>(h1, rW2, b2, x, out, MQ, Dm, Ff, 1.f);
}